// round 5
// baseline (speedup 1.0000x reference)
#include <cuda_runtime.h>
#include <cuda_fp16.h>

#define NN 50000
#define EE 1600000
#define RR 50
#define BB 30
#define HH 16
#define CC 4
#define NH2 (NN * HH / 2)   // 400000 float2 columns

// ---------------- scratch (device globals; no allocation) ----------------
__device__ uint4  g_w1h[(size_t)RR * NN * 2];      // [R,N,H] fp16: 32B/row, 80MB
__device__ float4 g_w2[RR * HH * CC / 4];          // [R,H,C]
__device__ uint4  g_xsumh[NN * 2];                 // layer1 accumulator, fp16
__device__ float4 g_x[NN * HH / 4];                // relu'd hidden features (fp32)
__device__ float  g_cnt[NN];                       // in-degree (float)
__device__ float4 g_osum[NN];                      // layer2 accumulator [N,C] fp32

// fp32 v4 reduction
__device__ __forceinline__ void red4(float4* p, float4 v) {
    asm volatile("red.global.add.v4.f32 [%0], {%1, %2, %3, %4};"
                 :: "l"(p), "f"(v.x), "f"(v.y), "f"(v.z), "f"(v.w)
                 : "memory");
}
// fp16x2 v4 reduction: adds 8 packed halves in one atomic op
__device__ __forceinline__ void red4h(uint4* p, uint4 v) {
    asm volatile("red.global.add.noftz.v4.f16x2 [%0], {%1, %2, %3, %4};"
                 :: "l"(p), "r"(v.x), "r"(v.y), "r"(v.z), "r"(v.w)
                 : "memory");
}

__device__ __forceinline__ void fma4(float4& a, float s, float4 w) {
    a.x += s * w.x; a.y += s * w.y; a.z += s * w.z; a.w += s * w.w;
}

// ---- packed f32x2 helpers ----
__device__ __forceinline__ unsigned long long pack2(float x, float y) {
    unsigned long long r;
    asm("mov.b64 %0, {%1, %2};" : "=l"(r) : "f"(x), "f"(y));
    return r;
}
__device__ __forceinline__ void unpack2(unsigned long long v, float& x, float& y) {
    asm("mov.b64 {%0, %1}, %2;" : "=f"(x), "=f"(y) : "l"(v));
}
__device__ __forceinline__ void fma2(unsigned long long& d,
                                     unsigned long long a, unsigned long long b) {
    asm("fma.rn.f32x2 %0, %1, %2, %0;" : "+l"(d) : "l"(a), "l"(b));
}

// ---------------- K0: zero the accumulators ----------------
__global__ void k_zero() {
    int i = blockIdx.x * blockDim.x + threadIdx.x;
    uint4 zu = make_uint4(0u, 0u, 0u, 0u);
    if (i < NN * 2) g_xsumh[i] = zu;
    if (i < NN) { g_cnt[i] = 0.f; g_osum[i] = make_float4(0.f, 0.f, 0.f, 0.f); }
}

// ---------------- K_w2: w2[r,h,c] = sum_b comp2[r,b] * basis2[b,h,c] ----------------
__global__ void k_w2(const float* __restrict__ comp2, const float* __restrict__ basis2) {
    __shared__ float sc[RR * BB];
    __shared__ float sb[BB * HH * CC];
    for (int i = threadIdx.x; i < RR * BB; i += blockDim.x) sc[i] = comp2[i];
    for (int i = threadIdx.x; i < BB * HH * CC; i += blockDim.x) sb[i] = basis2[i];
    __syncthreads();
    float* w2f = (float*)g_w2;
    for (int i = threadIdx.x; i < RR * HH * CC; i += blockDim.x) {
        int r = i / (HH * CC);
        int hc = i % (HH * CC);
        float acc = 0.f;
        #pragma unroll
        for (int b = 0; b < BB; b++) acc += sc[r * BB + b] * sb[b * HH * CC + hc];
        w2f[i] = acc;
    }
}

// ---------------- K1: w1[r,n,h] = sum_b comp1[r,b] * basis1[b,n,h], stored fp16 ----------------
// One thread per float2 column: basis = 30 u64 regs (no spills), inner loop =
// LDS.64 broadcast of packed (c,c) + one fma.rn.f32x2 per b. FMA-pipe bound.
__global__ void __launch_bounds__(128, 4) k_w1(const float2* __restrict__ basis1,
                                               const float* __restrict__ comp1) {
    __shared__ unsigned long long scc[RR * BB];   // 12 KB, (c,c) packed
    for (int i = threadIdx.x; i < RR * BB; i += blockDim.x) {
        float c = comp1[i];
        scc[i] = pack2(c, c);
    }
    __syncthreads();

    int i2 = blockIdx.x * blockDim.x + threadIdx.x;
    if (i2 >= NH2) return;

    unsigned long long bv[BB];
    #pragma unroll
    for (int b = 0; b < BB; b++) {
        float2 v = basis1[(size_t)b * NH2 + i2];
        bv[b] = pack2(v.x, v.y);
    }

    int n  = i2 >> 3;          // node
    int h2 = i2 & 7;           // which half2 pair within the 16-wide row
    unsigned int* outp = (unsigned int*)g_w1h;

    for (int r = 0; r < RR; r++) {
        unsigned long long acc = 0ull;
        const unsigned long long* cr = &scc[r * BB];
        #pragma unroll
        for (int b = 0; b < BB; b++) fma2(acc, cr[b], bv[b]);
        float f0, f1;
        unpack2(acc, f0, f1);
        __half2 h = __floats2half2_rn(f0, f1);
        outp[(((size_t)r * NN + n) << 3) + h2] = *(unsigned int*)&h;
    }
}

// ---------------- K2: layer-1 edge pass: gather fp16 w1 row (32B), fp16x2 vector RED ----------------
__global__ void k_edge1(const int* __restrict__ ei, const int* __restrict__ et) {
    int e = blockIdx.x * blockDim.x + threadIdx.x;
    if (e >= EE) return;
    int s = ei[e];
    int d = ei[EE + e];
    int t = et[e];
    const uint4* row = g_w1h + ((size_t)t * NN + s) * 2;
    uint4 a = row[0], b = row[1];
    uint4* dst = g_xsumh + d * 2;
    red4h(dst + 0, a);
    red4h(dst + 1, b);
    atomicAdd(&g_cnt[d], 1.0f);
}

// ---------------- K3: x = relu(xsum/max(cnt,1) + root1 + bias1) ----------------
__global__ void k_x(const float4* __restrict__ root1, const float4* __restrict__ bias1) {
    int n = blockIdx.x * blockDim.x + threadIdx.x;
    if (n >= NN) return;
    float inv = 1.f / fmaxf(g_cnt[n], 1.f);
    uint4 a = g_xsumh[n * 2];
    uint4 b = g_xsumh[n * 2 + 1];
    unsigned int w[8] = {a.x, a.y, a.z, a.w, b.x, b.y, b.z, b.w};
    #pragma unroll
    for (int j = 0; j < 4; j++) {
        float2 lo = __half22float2(*(__half2*)&w[j * 2]);
        float2 hi = __half22float2(*(__half2*)&w[j * 2 + 1]);
        float4 rv = root1[n * 4 + j];
        float4 bv = bias1[j];
        float4 o;
        o.x = fmaxf(lo.x * inv + rv.x + bv.x, 0.f);
        o.y = fmaxf(lo.y * inv + rv.y + bv.y, 0.f);
        o.z = fmaxf(hi.x * inv + rv.z + bv.z, 0.f);
        o.w = fmaxf(hi.y * inv + rv.w + bv.w, 0.f);
        g_x[n * 4 + j] = o;
    }
}

// ---------------- K4: layer-2 edge pass: msg = x[src] @ w2[t], scatter-add ----------------
__global__ void k_edge2(const int* __restrict__ ei, const int* __restrict__ et) {
    __shared__ float4 sw2[RR * HH];  // 12.8 KB
    for (int i = threadIdx.x; i < RR * HH; i += blockDim.x) sw2[i] = g_w2[i];
    __syncthreads();

    int e = blockIdx.x * blockDim.x + threadIdx.x;
    if (e >= EE) return;
    int s = ei[e];
    int d = ei[EE + e];
    int t = et[e];

    const float4* xr = g_x + s * 4;
    float4 x0 = xr[0], x1 = xr[1], x2 = xr[2], x3 = xr[3];
    const float4* w = &sw2[t * HH];

    float4 acc = make_float4(0.f, 0.f, 0.f, 0.f);
    fma4(acc, x0.x, w[0]);  fma4(acc, x0.y, w[1]);  fma4(acc, x0.z, w[2]);  fma4(acc, x0.w, w[3]);
    fma4(acc, x1.x, w[4]);  fma4(acc, x1.y, w[5]);  fma4(acc, x1.z, w[6]);  fma4(acc, x1.w, w[7]);
    fma4(acc, x2.x, w[8]);  fma4(acc, x2.y, w[9]);  fma4(acc, x2.z, w[10]); fma4(acc, x2.w, w[11]);
    fma4(acc, x3.x, w[12]); fma4(acc, x3.y, w[13]); fma4(acc, x3.z, w[14]); fma4(acc, x3.w, w[15]);

    red4(&g_osum[d], acc);
}

// ---------------- K5: out = log_softmax(osum/max(cnt,1) + x @ root2 + bias2) ----------------
__global__ void k_out(const float4* __restrict__ root2, const float4* __restrict__ bias2,
                      float4* __restrict__ out) {
    __shared__ float4 sr2[HH];
    __shared__ float4 sb2;
    if (threadIdx.x < HH) sr2[threadIdx.x] = root2[threadIdx.x];
    if (threadIdx.x == 0) sb2 = bias2[0];
    __syncthreads();

    int n = blockIdx.x * blockDim.x + threadIdx.x;
    if (n >= NN) return;

    float inv = 1.f / fmaxf(g_cnt[n], 1.f);
    float4 os = g_osum[n];
    float4 acc;
    acc.x = os.x * inv + sb2.x;
    acc.y = os.y * inv + sb2.y;
    acc.z = os.z * inv + sb2.z;
    acc.w = os.w * inv + sb2.w;

    const float4* xr = g_x + n * 4;
    #pragma unroll
    for (int j = 0; j < 4; j++) {
        float4 xv = xr[j];
        fma4(acc, xv.x, sr2[j * 4 + 0]);
        fma4(acc, xv.y, sr2[j * 4 + 1]);
        fma4(acc, xv.z, sr2[j * 4 + 2]);
        fma4(acc, xv.w, sr2[j * 4 + 3]);
    }

    float m = fmaxf(fmaxf(acc.x, acc.y), fmaxf(acc.z, acc.w));
    float se = expf(acc.x - m) + expf(acc.y - m) + expf(acc.z - m) + expf(acc.w - m);
    float l = m + logf(se);
    float4 o;
    o.x = acc.x - l; o.y = acc.y - l; o.z = acc.z - l; o.w = acc.w - l;
    out[n] = o;
}

// ---------------- launcher ----------------
extern "C" void kernel_launch(void* const* d_in, const int* in_sizes, int n_in,
                              void* d_out, int out_size) {
    const int*    ei        = (const int*)d_in[0];         // edge_index [2,E] int32
    const int*    et        = (const int*)d_in[1];         // edge_type  [E]   int32
    // d_in[2] edge_norm: unused by the reference forward
    const float*  basis1    = (const float*)d_in[3];       // [B,N,H]
    const float*  comp1     = (const float*)d_in[4];       // [R,B]
    const float4* root1     = (const float4*)d_in[5];      // [N,H]
    const float4* bias1     = (const float4*)d_in[6];      // [H]
    const float*  basis2    = (const float*)d_in[7];       // [B,H,C]
    const float*  comp2     = (const float*)d_in[8];       // [R,B]
    const float4* root2     = (const float4*)d_in[9];      // [H,C]
    const float4* bias2     = (const float4*)d_in[10];     // [C]
    float4* out = (float4*)d_out;

    (void)in_sizes; (void)n_in; (void)out_size;

    k_zero <<<(NN * 2 + 255) / 256, 256>>>();
    k_w2   <<<1, 256>>>(comp2, basis2);
    k_w1   <<<(NH2 + 127) / 128, 128>>>((const float2*)basis1, comp1);
    k_edge1<<<(EE + 255) / 256, 256>>>(ei, et);
    k_x    <<<(NN + 255) / 256, 256>>>(root1, bias1);
    k_edge2<<<(EE + 255) / 256, 256>>>(ei, et);
    k_out  <<<(NN + 255) / 256, 256>>>(root2, bias2, out);
}

// round 6
// speedup vs baseline: 1.1199x; 1.1199x over previous
#include <cuda_runtime.h>
#include <cuda_fp16.h>

#define NN 50000
#define EE 1600000
#define RR 50
#define BB 30
#define HH 16
#define CC 4
#define NH4 (NN * HH / 4)   // 200000 4-half chunks

// ---------------- scratch (device globals; no allocation) ----------------
__device__ uint4  g_w1h[(size_t)RR * NN * 2];      // [R,N,H] fp16: 32B/row, 80MB
__device__ float4 g_w2[RR * HH * CC / 4];          // [R,H,C]
__device__ uint4  g_xsumh[NN * 2];                 // layer1 accumulator, fp16
__device__ float4 g_x[NN * HH / 4];                // relu'd hidden features (fp32)
__device__ float  g_cnt[NN];                       // in-degree (float)
__device__ float4 g_osum[NN];                      // layer2 accumulator [N,C] fp32

// fp32 v4 reduction
__device__ __forceinline__ void red4(float4* p, float4 v) {
    asm volatile("red.global.add.v4.f32 [%0], {%1, %2, %3, %4};"
                 :: "l"(p), "f"(v.x), "f"(v.y), "f"(v.z), "f"(v.w)
                 : "memory");
}
// fp16x2 v4 reduction: adds 8 packed halves in one atomic op
__device__ __forceinline__ void red4h(uint4* p, uint4 v) {
    asm volatile("red.global.add.noftz.v4.f16x2 [%0], {%1, %2, %3, %4};"
                 :: "l"(p), "r"(v.x), "r"(v.y), "r"(v.z), "r"(v.w)
                 : "memory");
}

__device__ __forceinline__ void fma4(float4& a, float s, float4 w) {
    a.x += s * w.x; a.y += s * w.y; a.z += s * w.z; a.w += s * w.w;
}

__device__ __forceinline__ unsigned int h2bits(__half2 h) {
    return *(unsigned int*)&h;
}
__device__ __forceinline__ __half2 bits2h(unsigned int u) {
    return *(__half2*)&u;
}

// ---------------- K0: zero the accumulators ----------------
__global__ void k_zero() {
    int i = blockIdx.x * blockDim.x + threadIdx.x;
    uint4 zu = make_uint4(0u, 0u, 0u, 0u);
    if (i < NN * 2) g_xsumh[i] = zu;
    if (i < NN) { g_cnt[i] = 0.f; g_osum[i] = make_float4(0.f, 0.f, 0.f, 0.f); }
}

// ---------------- K_w2: w2[r,h,c] = sum_b comp2[r,b] * basis2[b,h,c] ----------------
__global__ void k_w2(const float* __restrict__ comp2, const float* __restrict__ basis2) {
    __shared__ float sc[RR * BB];
    __shared__ float sb[BB * HH * CC];
    for (int i = threadIdx.x; i < RR * BB; i += blockDim.x) sc[i] = comp2[i];
    for (int i = threadIdx.x; i < BB * HH * CC; i += blockDim.x) sb[i] = basis2[i];
    __syncthreads();
    float* w2f = (float*)g_w2;
    for (int i = threadIdx.x; i < RR * HH * CC; i += blockDim.x) {
        int r = i / (HH * CC);
        int hc = i % (HH * CC);
        float acc = 0.f;
        #pragma unroll
        for (int b = 0; b < BB; b++) acc += sc[r * BB + b] * sb[b * HH * CC + hc];
        w2f[i] = acc;
    }
}

// ---------------- K1: w1[r,n,h] = sum_b comp1[r,b] * basis1[b,n,h]  (fp16 HFMA2) ----------------
// One thread per 4 halves. Basis column held as 2x half2 regs (60 regs),
// coefficients pre-packed as half2(c,c) in smem. Inner loop: LDS.32 broadcast
// + 2x HFMA2 (native packed, 64 lane-FMA/instr). Output stored directly.
__global__ void __launch_bounds__(128, 4) k_w1(const float4* __restrict__ basis1,
                                               const float* __restrict__ comp1) {
    __shared__ unsigned int sch[RR * BB];   // 6 KB: half2(c,c)
    for (int i = threadIdx.x; i < RR * BB; i += blockDim.x) {
        float c = comp1[i];
        sch[i] = h2bits(__floats2half2_rn(c, c));
    }
    __syncthreads();

    int i4 = blockIdx.x * blockDim.x + threadIdx.x;
    if (i4 >= NH4) return;

    unsigned int bv0[BB], bv1[BB];
    #pragma unroll
    for (int b = 0; b < BB; b++) {
        float4 v = basis1[(size_t)b * NH4 + i4];
        bv0[b] = h2bits(__floats2half2_rn(v.x, v.y));
        bv1[b] = h2bits(__floats2half2_rn(v.z, v.w));
    }

    int n = i4 >> 2;           // node
    int q = i4 & 3;            // quarter of the 16-half row
    uint2* outp = (uint2*)g_w1h;

    for (int r = 0; r < RR; r++) {
        __half2 a0 = __floats2half2_rn(0.f, 0.f);
        __half2 a1 = a0;
        const unsigned int* cr = &sch[r * BB];
        #pragma unroll
        for (int b = 0; b < BB; b++) {
            __half2 cc = bits2h(cr[b]);
            a0 = __hfma2(cc, bits2h(bv0[b]), a0);
            a1 = __hfma2(cc, bits2h(bv1[b]), a1);
        }
        uint2 o;
        o.x = h2bits(a0);
        o.y = h2bits(a1);
        outp[(((size_t)r * NN + n) << 2) + q] = o;
    }
}

// ---------------- K2: layer-1 edge pass: gather fp16 w1 row (32B), fp16x2 vector RED ----------------
__global__ void k_edge1(const int* __restrict__ ei, const int* __restrict__ et) {
    int e = blockIdx.x * blockDim.x + threadIdx.x;
    if (e >= EE) return;
    int s = ei[e];
    int d = ei[EE + e];
    int t = et[e];
    const uint4* row = g_w1h + ((size_t)t * NN + s) * 2;
    uint4 a = row[0], b = row[1];
    uint4* dst = g_xsumh + d * 2;
    red4h(dst + 0, a);
    red4h(dst + 1, b);
    atomicAdd(&g_cnt[d], 1.0f);
}

// ---------------- K3: x = relu(xsum/max(cnt,1) + root1 + bias1) ----------------
__global__ void k_x(const float4* __restrict__ root1, const float4* __restrict__ bias1) {
    int n = blockIdx.x * blockDim.x + threadIdx.x;
    if (n >= NN) return;
    float inv = 1.f / fmaxf(g_cnt[n], 1.f);
    uint4 a = g_xsumh[n * 2];
    uint4 b = g_xsumh[n * 2 + 1];
    unsigned int w[8] = {a.x, a.y, a.z, a.w, b.x, b.y, b.z, b.w};
    #pragma unroll
    for (int j = 0; j < 4; j++) {
        float2 lo = __half22float2(bits2h(w[j * 2]));
        float2 hi = __half22float2(bits2h(w[j * 2 + 1]));
        float4 rv = root1[n * 4 + j];
        float4 bv = bias1[j];
        float4 o;
        o.x = fmaxf(lo.x * inv + rv.x + bv.x, 0.f);
        o.y = fmaxf(lo.y * inv + rv.y + bv.y, 0.f);
        o.z = fmaxf(hi.x * inv + rv.z + bv.z, 0.f);
        o.w = fmaxf(hi.y * inv + rv.w + bv.w, 0.f);
        g_x[n * 4 + j] = o;
    }
}

// ---------------- K4: layer-2 edge pass: msg = x[src] @ w2[t], scatter-add ----------------
__global__ void k_edge2(const int* __restrict__ ei, const int* __restrict__ et) {
    __shared__ float4 sw2[RR * HH];  // 12.8 KB
    for (int i = threadIdx.x; i < RR * HH; i += blockDim.x) sw2[i] = g_w2[i];
    __syncthreads();

    int e = blockIdx.x * blockDim.x + threadIdx.x;
    if (e >= EE) return;
    int s = ei[e];
    int d = ei[EE + e];
    int t = et[e];

    const float4* xr = g_x + s * 4;
    float4 x0 = xr[0], x1 = xr[1], x2 = xr[2], x3 = xr[3];
    const float4* w = &sw2[t * HH];

    float4 acc = make_float4(0.f, 0.f, 0.f, 0.f);
    fma4(acc, x0.x, w[0]);  fma4(acc, x0.y, w[1]);  fma4(acc, x0.z, w[2]);  fma4(acc, x0.w, w[3]);
    fma4(acc, x1.x, w[4]);  fma4(acc, x1.y, w[5]);  fma4(acc, x1.z, w[6]);  fma4(acc, x1.w, w[7]);
    fma4(acc, x2.x, w[8]);  fma4(acc, x2.y, w[9]);  fma4(acc, x2.z, w[10]); fma4(acc, x2.w, w[11]);
    fma4(acc, x3.x, w[12]); fma4(acc, x3.y, w[13]); fma4(acc, x3.z, w[14]); fma4(acc, x3.w, w[15]);

    red4(&g_osum[d], acc);
}

// ---------------- K5: out = log_softmax(osum/max(cnt,1) + x @ root2 + bias2) ----------------
__global__ void k_out(const float4* __restrict__ root2, const float4* __restrict__ bias2,
                      float4* __restrict__ out) {
    __shared__ float4 sr2[HH];
    __shared__ float4 sb2;
    if (threadIdx.x < HH) sr2[threadIdx.x] = root2[threadIdx.x];
    if (threadIdx.x == 0) sb2 = bias2[0];
    __syncthreads();

    int n = blockIdx.x * blockDim.x + threadIdx.x;
    if (n >= NN) return;

    float inv = 1.f / fmaxf(g_cnt[n], 1.f);
    float4 os = g_osum[n];
    float4 acc;
    acc.x = os.x * inv + sb2.x;
    acc.y = os.y * inv + sb2.y;
    acc.z = os.z * inv + sb2.z;
    acc.w = os.w * inv + sb2.w;

    const float4* xr = g_x + n * 4;
    #pragma unroll
    for (int j = 0; j < 4; j++) {
        float4 xv = xr[j];
        fma4(acc, xv.x, sr2[j * 4 + 0]);
        fma4(acc, xv.y, sr2[j * 4 + 1]);
        fma4(acc, xv.z, sr2[j * 4 + 2]);
        fma4(acc, xv.w, sr2[j * 4 + 3]);
    }

    float m = fmaxf(fmaxf(acc.x, acc.y), fmaxf(acc.z, acc.w));
    float se = expf(acc.x - m) + expf(acc.y - m) + expf(acc.z - m) + expf(acc.w - m);
    float l = m + logf(se);
    float4 o;
    o.x = acc.x - l; o.y = acc.y - l; o.z = acc.z - l; o.w = acc.w - l;
    out[n] = o;
}

// ---------------- launcher ----------------
extern "C" void kernel_launch(void* const* d_in, const int* in_sizes, int n_in,
                              void* d_out, int out_size) {
    const int*    ei        = (const int*)d_in[0];         // edge_index [2,E] int32
    const int*    et        = (const int*)d_in[1];         // edge_type  [E]   int32
    // d_in[2] edge_norm: unused by the reference forward
    const float*  basis1    = (const float*)d_in[3];       // [B,N,H]
    const float*  comp1     = (const float*)d_in[4];       // [R,B]
    const float4* root1     = (const float4*)d_in[5];      // [N,H]
    const float4* bias1     = (const float4*)d_in[6];      // [H]
    const float*  basis2    = (const float*)d_in[7];       // [B,H,C]
    const float*  comp2     = (const float*)d_in[8];       // [R,B]
    const float4* root2     = (const float4*)d_in[9];      // [H,C]
    const float4* bias2     = (const float4*)d_in[10];     // [C]
    float4* out = (float4*)d_out;

    (void)in_sizes; (void)n_in; (void)out_size;

    k_zero <<<(NN * 2 + 255) / 256, 256>>>();
    k_w2   <<<1, 256>>>(comp2, basis2);
    k_w1   <<<(NH4 + 127) / 128, 128>>>((const float4*)basis1, comp1);
    k_edge1<<<(EE + 255) / 256, 256>>>(ei, et);
    k_x    <<<(NN + 255) / 256, 256>>>(root1, bias1);
    k_edge2<<<(EE + 255) / 256, 256>>>(ei, et);
    k_out  <<<(NN + 255) / 256, 256>>>(root2, bias2, out);
}